// round 7
// baseline (speedup 1.0000x reference)
#include <cuda_runtime.h>
#include <math.h>
#include <stdint.h>

// ---------------------------------------------------------------------------
// Problem constants (MonArcHeadLayer): B=2, S=1024, HIDDEN=2048, 32 heads x 64,
// ROT_DIM=16, D_FF=8192, fp32 end-to-end.
// ---------------------------------------------------------------------------
#define HIDDEN  2048
#define NHEADS  32
#define HDIM    64
#define ROT     16
#define DFF     8192
#define SQ      1024
#define BATCH   2
#define NTOK    (BATCH * SQ)     // 2048 tokens
#define EPS     1e-5f

// ---------------------------------------------------------------------------
// Static scratch (no allocation allowed in kernel_launch)
// ---------------------------------------------------------------------------
__device__ float g_xln [NTOK * HIDDEN];   // LN1 output
__device__ float g_q   [NTOK * HIDDEN];   // Q proj (layout [t, h*64+d])
__device__ float g_k   [NTOK * HIDDEN];
__device__ float g_v   [NTOK * HIDDEN];
__device__ float g_ctx [NTOK * HIDDEN];   // attention context
__device__ float g_h   [NTOK * HIDDEN];   // residual + attn_out
__device__ float g_yln [NTOK * HIDDEN];   // LN2 output
__device__ float g_gate[NTOK * DFF];      // gate proj -> reused for activation
__device__ float g_up  [NTOK * DFF];      // up proj

// ---------------------------------------------------------------------------
// LayerNorm: one block per token, 256 threads
// ---------------------------------------------------------------------------
__global__ __launch_bounds__(256) void ln_kernel(
    const float* __restrict__ x, const float* __restrict__ w,
    const float* __restrict__ b, float* __restrict__ out)
{
    int t = blockIdx.x;
    const float* xr = x + (size_t)t * HIDDEN;
    float* orow = out + (size_t)t * HIDDEN;

    float s = 0.f, ss = 0.f;
    for (int i = threadIdx.x; i < HIDDEN; i += 256) {
        float v = xr[i];
        s += v; ss += v * v;
    }
    __shared__ float red_s[8], red_ss[8];
    #pragma unroll
    for (int o = 16; o; o >>= 1) {
        s  += __shfl_xor_sync(0xffffffffu, s,  o);
        ss += __shfl_xor_sync(0xffffffffu, ss, o);
    }
    int wid = threadIdx.x >> 5, lid = threadIdx.x & 31;
    if (lid == 0) { red_s[wid] = s; red_ss[wid] = ss; }
    __syncthreads();
    if (wid == 0) {
        s  = (lid < 8) ? red_s[lid]  : 0.f;
        ss = (lid < 8) ? red_ss[lid] : 0.f;
        #pragma unroll
        for (int o = 4; o; o >>= 1) {
            s  += __shfl_xor_sync(0xffffffffu, s,  o);
            ss += __shfl_xor_sync(0xffffffffu, ss, o);
        }
        if (lid == 0) { red_s[0] = s * (1.f / HIDDEN); red_ss[0] = ss * (1.f / HIDDEN); }
    }
    __syncthreads();
    float mu  = red_s[0];
    float var = red_ss[0] - mu * mu;
    float inv = rsqrtf(var + EPS);
    for (int i = threadIdx.x; i < HIDDEN; i += 256)
        orow[i] = (xr[i] - mu) * inv * w[i] + b[i];
}

// ---------------------------------------------------------------------------
// SGEMM (NT): C[M,N] = A[M,K] * B[N,K]^T  (+ optional elementwise add)
// A row-major [M,K], B row-major [N,K]. 128x128 block, 8x8 per thread,
// 256 threads, BK=16, global-load prefetch, padded smem.
// All dims here are multiples of 128/16 so no edge guards.
// ---------------------------------------------------------------------------
#define BM 128
#define BN 128
#define BKS 16

__global__ __launch_bounds__(256) void sgemm_nt(
    const float* __restrict__ A, const float* __restrict__ B,
    float* __restrict__ C, const float* __restrict__ add,
    int M, int N, int K)
{
    __shared__ __align__(16) float As[BKS][BM + 4];
    __shared__ __align__(16) float Bs[BKS][BN + 4];

    int tid = threadIdx.x;
    int tx = tid & 15;        // 0..15 -> n micro position
    int ty = tid >> 4;        // 0..15 -> m micro position
    int m0 = blockIdx.y * BM;
    int n0 = blockIdx.x * BN;

    float acc[8][8];
    #pragma unroll
    for (int i = 0; i < 8; i++)
        #pragma unroll
        for (int j = 0; j < 8; j++) acc[i][j] = 0.f;

    int lrow = tid >> 2;            // 0..63
    int lcol = (tid & 3) * 4;       // 0,4,8,12
    const float* Ap = A + (size_t)(m0 + lrow) * K + lcol;
    const float* Bp = B + (size_t)(n0 + lrow) * K + lcol;

    // prefetch first tile
    float4 a0 = *(const float4*)(Ap);
    float4 a1 = *(const float4*)(Ap + (size_t)64 * K);
    float4 b0 = *(const float4*)(Bp);
    float4 b1 = *(const float4*)(Bp + (size_t)64 * K);

    for (int k0 = 0; k0 < K; k0 += BKS) {
        As[lcol + 0][lrow]      = a0.x; As[lcol + 1][lrow]      = a0.y;
        As[lcol + 2][lrow]      = a0.z; As[lcol + 3][lrow]      = a0.w;
        As[lcol + 0][lrow + 64] = a1.x; As[lcol + 1][lrow + 64] = a1.y;
        As[lcol + 2][lrow + 64] = a1.z; As[lcol + 3][lrow + 64] = a1.w;
        Bs[lcol + 0][lrow]      = b0.x; Bs[lcol + 1][lrow]      = b0.y;
        Bs[lcol + 2][lrow]      = b0.z; Bs[lcol + 3][lrow]      = b0.w;
        Bs[lcol + 0][lrow + 64] = b1.x; Bs[lcol + 1][lrow + 64] = b1.y;
        Bs[lcol + 2][lrow + 64] = b1.z; Bs[lcol + 3][lrow + 64] = b1.w;
        __syncthreads();

        int kn = k0 + BKS;
        if (kn < K) {
            a0 = *(const float4*)(Ap + kn);
            a1 = *(const float4*)(Ap + (size_t)64 * K + kn);
            b0 = *(const float4*)(Bp + kn);
            b1 = *(const float4*)(Bp + (size_t)64 * K + kn);
        }

        #pragma unroll
        for (int k = 0; k < BKS; k++) {
            float4 av0 = *(const float4*)&As[k][ty * 4];
            float4 av1 = *(const float4*)&As[k][64 + ty * 4];
            float4 bv0 = *(const float4*)&Bs[k][tx * 4];
            float4 bv1 = *(const float4*)&Bs[k][64 + tx * 4];
            float ar[8] = {av0.x, av0.y, av0.z, av0.w, av1.x, av1.y, av1.z, av1.w};
            float br[8] = {bv0.x, bv0.y, bv0.z, bv0.w, bv1.x, bv1.y, bv1.z, bv1.w};
            #pragma unroll
            for (int i = 0; i < 8; i++)
                #pragma unroll
                for (int j = 0; j < 8; j++)
                    acc[i][j] = fmaf(ar[i], br[j], acc[i][j]);
        }
        __syncthreads();
    }

    // epilogue
    #pragma unroll
    for (int i = 0; i < 8; i++) {
        int m = m0 + ((i < 4) ? (ty * 4 + i) : (64 + ty * 4 + i - 4));
        #pragma unroll
        for (int jh = 0; jh < 2; jh++) {
            int n = n0 + jh * 64 + tx * 4;
            float4 r;
            r.x = acc[i][jh * 4 + 0];
            r.y = acc[i][jh * 4 + 1];
            r.z = acc[i][jh * 4 + 2];
            r.w = acc[i][jh * 4 + 3];
            if (add) {
                float4 ad = *(const float4*)(add + (size_t)m * N + n);
                r.x += ad.x; r.y += ad.y; r.z += ad.z; r.w += ad.w;
            }
            *(float4*)(C + (size_t)m * N + n) = r;
        }
    }
}

// ---------------------------------------------------------------------------
// RoPE in-place on first ROT dims of every head. One thread per (token, head).
// ---------------------------------------------------------------------------
__global__ void rope_kernel(float* __restrict__ qk, const int* __restrict__ pos_ids)
{
    int idx = blockIdx.x * blockDim.x + threadIdx.x;
    if (idx >= NTOK * NHEADS) return;
    int t = idx / NHEADS, h = idx % NHEADS;
    float pos = (float)pos_ids[t];
    float* p = qk + (size_t)t * HIDDEN + h * HDIM;

    float x[ROT];
    #pragma unroll
    for (int j = 0; j < ROT; j++) x[j] = p[j];

    #pragma unroll
    for (int i = 0; i < ROT / 2; i++) {
        float invf = powf(10000.f, -(float)i / (ROT / 2));
        float f = pos * invf;
        float c = cosf(f), s = sinf(f);
        float lo = x[i], hi = x[i + ROT / 2];
        p[i]           = lo * c - hi * s;   // x*cos + (-x_hi)*sin
        p[i + ROT / 2] = hi * c + lo * s;   // x*cos + ( x_lo)*sin
    }
}

// ---------------------------------------------------------------------------
// Flash attention fp32. One block = (128 q-rows, one head, one batch).
// One thread owns one q-row: q[64] and o[64] in registers, online softmax.
// K/V/mask staged through shared memory, K tile = 32 rows per iteration.
// ---------------------------------------------------------------------------
#define BQ  128
#define BKT 32

__global__ __launch_bounds__(128) void attn_kernel(const float* __restrict__ mask)
{
    __shared__ __align__(16) float Ks[BKT][HDIM];
    __shared__ __align__(16) float Vs[BKT][HDIM];
    __shared__ float Ms[BQ][BKT + 1];     // padded: conflict-free [tid][kj] reads

    int b  = blockIdx.z;
    int h  = blockIdx.y;
    int q0 = blockIdx.x * BQ;
    int tid = threadIdx.x;
    int qi = q0 + tid;
    int t  = b * SQ + qi;

    const float* qrow  = g_q + (size_t)t * HIDDEN + h * HDIM;
    const float* kbase = g_k + (size_t)(b * SQ) * HIDDEN + h * HDIM;
    const float* vbase = g_v + (size_t)(b * SQ) * HIDDEN + h * HDIM;

    float4 qv[16], ov[16];
    #pragma unroll
    for (int i = 0; i < 16; i++) {
        qv[i] = *(const float4*)(qrow + i * 4);
        ov[i] = make_float4(0.f, 0.f, 0.f, 0.f);
    }
    float m = -1e30f, l = 0.f;
    const float scale = 0.125f;  // 1/sqrt(64)

    for (int k0 = 0; k0 < SQ; k0 += BKT) {
        // stage K/V tiles (32x64 each)
        for (int i = tid * 4; i < BKT * HDIM; i += 128 * 4) {
            int r = i >> 6, c = i & 63;
            *(float4*)&Ks[r][c] = *(const float4*)(kbase + (size_t)(k0 + r) * HIDDEN + c);
            *(float4*)&Vs[r][c] = *(const float4*)(vbase + (size_t)(k0 + r) * HIDDEN + c);
        }
        // stage mask tile (128 q x 32 k), coalesced along k
        for (int i = tid * 4; i < BQ * BKT; i += 128 * 4) {
            int r = i >> 5, c = i & 31;
            float4 mv = *(const float4*)(mask + ((size_t)(b * SQ + q0 + r)) * SQ + k0 + c);
            Ms[r][c + 0] = mv.x; Ms[r][c + 1] = mv.y;
            Ms[r][c + 2] = mv.z; Ms[r][c + 3] = mv.w;
        }
        __syncthreads();

        float sc[BKT];
        float tmax = m;
        #pragma unroll
        for (int kj = 0; kj < BKT; kj++) {
            float s = 0.f;
            #pragma unroll
            for (int d4 = 0; d4 < 16; d4++) {
                float4 kv = *(const float4*)&Ks[kj][d4 * 4];
                s = fmaf(qv[d4].x, kv.x, s);
                s = fmaf(qv[d4].y, kv.y, s);
                s = fmaf(qv[d4].z, kv.z, s);
                s = fmaf(qv[d4].w, kv.w, s);
            }
            s = s * scale + Ms[tid][kj];
            sc[kj] = s;
            tmax = fmaxf(tmax, s);
        }
        float corr = expf(m - tmax);   // first tile: exp(-inf)=0, o already 0
        m = tmax;
        l *= corr;
        #pragma unroll
        for (int i = 0; i < 16; i++) {
            ov[i].x *= corr; ov[i].y *= corr; ov[i].z *= corr; ov[i].w *= corr;
        }
        #pragma unroll
        for (int kj = 0; kj < BKT; kj++) {
            float e = expf(sc[kj] - m);
            l += e;
            #pragma unroll
            for (int d4 = 0; d4 < 16; d4++) {
                float4 vv = *(const float4*)&Vs[kj][d4 * 4];
                ov[d4].x = fmaf(e, vv.x, ov[d4].x);
                ov[d4].y = fmaf(e, vv.y, ov[d4].y);
                ov[d4].z = fmaf(e, vv.z, ov[d4].z);
                ov[d4].w = fmaf(e, vv.w, ov[d4].w);
            }
        }
        __syncthreads();
    }

    float inv = 1.f / l;
    float* orow = g_ctx + (size_t)t * HIDDEN + h * HDIM;
    #pragma unroll
    for (int i = 0; i < 16; i++) {
        float4 r = make_float4(ov[i].x * inv, ov[i].y * inv, ov[i].z * inv, ov[i].w * inv);
        *(float4*)(orow + i * 4) = r;
    }
}

// ---------------------------------------------------------------------------
// SwiGLU activation: g = silu(g) * u, elementwise, vectorized
// ---------------------------------------------------------------------------
__global__ void silu_mul_kernel(float* __restrict__ g, const float* __restrict__ u, int n4)
{
    int i = blockIdx.x * blockDim.x + threadIdx.x;
    if (i >= n4) return;
    float4 gv = ((const float4*)g)[i];
    float4 uv = ((const float4*)u)[i];
    gv.x = gv.x / (1.f + expf(-gv.x)) * uv.x;
    gv.y = gv.y / (1.f + expf(-gv.y)) * uv.y;
    gv.z = gv.z / (1.f + expf(-gv.z)) * uv.z;
    gv.w = gv.w / (1.f + expf(-gv.w)) * uv.w;
    ((float4*)g)[i] = gv;
}

// ---------------------------------------------------------------------------
// Launch
// Inputs (metadata order): hidden_states, memory, attention_mask, position_ids,
// Wq, Wk, Wv, Wo, ln1_w, ln1_b, ln2_w, ln2_b, gate_w, up_w, down_w
// ---------------------------------------------------------------------------
extern "C" void kernel_launch(void* const* d_in, const int* in_sizes, int n_in,
                              void* d_out, int out_size)
{
    const float* hs    = (const float*)d_in[0];
    const float* mem   = (const float*)d_in[1];
    const float* mask  = (const float*)d_in[2];
    const int*   pos   = (const int*)  d_in[3];
    const float* Wq    = (const float*)d_in[4];
    const float* Wk    = (const float*)d_in[5];
    const float* Wv    = (const float*)d_in[6];
    const float* Wo    = (const float*)d_in[7];
    const float* ln1w  = (const float*)d_in[8];
    const float* ln1b  = (const float*)d_in[9];
    const float* ln2w  = (const float*)d_in[10];
    const float* ln2b  = (const float*)d_in[11];
    const float* gatew = (const float*)d_in[12];
    const float* upw   = (const float*)d_in[13];
    const float* downw = (const float*)d_in[14];
    float* out = (float*)d_out;

    float *xln, *q, *k, *v, *ctx, *h, *yln, *gate, *up;
    cudaGetSymbolAddress((void**)&xln,  g_xln);
    cudaGetSymbolAddress((void**)&q,    g_q);
    cudaGetSymbolAddress((void**)&k,    g_k);
    cudaGetSymbolAddress((void**)&v,    g_v);
    cudaGetSymbolAddress((void**)&ctx,  g_ctx);
    cudaGetSymbolAddress((void**)&h,    g_h);
    cudaGetSymbolAddress((void**)&yln,  g_yln);
    cudaGetSymbolAddress((void**)&gate, g_gate);
    cudaGetSymbolAddress((void**)&up,   g_up);

    // 1. LN1
    ln_kernel<<<NTOK, 256>>>(hs, ln1w, ln1b, xln);

    // 2. Q/K/V projections (NT gemm: x @ W^T)
    dim3 g2048(HIDDEN / BN, NTOK / BM);
    sgemm_nt<<<g2048, 256>>>(xln, Wq, q, nullptr, NTOK, HIDDEN, HIDDEN);
    sgemm_nt<<<g2048, 256>>>(mem, Wk, k, nullptr, NTOK, HIDDEN, HIDDEN);
    sgemm_nt<<<g2048, 256>>>(mem, Wv, v, nullptr, NTOK, HIDDEN, HIDDEN);

    // 3. RoPE on q and k
    int nrope = NTOK * NHEADS;
    rope_kernel<<<(nrope + 255) / 256, 256>>>(q, pos);
    rope_kernel<<<(nrope + 255) / 256, 256>>>(k, pos);

    // 4. Attention
    attn_kernel<<<dim3(SQ / BQ, NHEADS, BATCH), 128>>>(mask);

    // 5. O projection + residual  (h = hs + ctx @ Wo^T)
    sgemm_nt<<<g2048, 256>>>(ctx, Wo, h, hs, NTOK, HIDDEN, HIDDEN);

    // 6. LN2
    ln_kernel<<<NTOK, 256>>>(h, ln2w, ln2b, yln);

    // 7. MLP gate/up
    dim3 g8192(DFF / BN, NTOK / BM);
    sgemm_nt<<<g8192, 256>>>(yln, gatew, gate, nullptr, NTOK, DFF, HIDDEN);
    sgemm_nt<<<g8192, 256>>>(yln, upw,   up,   nullptr, NTOK, DFF, HIDDEN);

    // 8. silu(gate) * up  -> gate (in place)
    int n4 = NTOK * DFF / 4;
    silu_mul_kernel<<<(n4 + 255) / 256, 256>>>(gate, up, n4);

    // 9. down projection + residual -> out
    sgemm_nt<<<g2048, 256>>>(gate, downw, out, h, NTOK, HIDDEN, DFF);

    (void)in_sizes; (void)n_in; (void)out_size;
}

// round 10
// speedup vs baseline: 1.9619x; 1.9619x over previous
#include <cuda_runtime.h>
#include <math.h>
#include <stdint.h>

// ---------------------------------------------------------------------------
// Problem constants (MonArcHeadLayer): B=2, S=1024, HIDDEN=2048, 32 heads x 64,
// ROT_DIM=16, D_FF=8192, fp32 end-to-end. GEMMs on tf32 tensor cores.
// ---------------------------------------------------------------------------
#define HIDDEN  2048
#define NHEADS  32
#define HDIM    64
#define ROT     16
#define DFF     8192
#define SQ      1024
#define BATCH   2
#define NTOK    (BATCH * SQ)     // 2048 tokens
#define EPS     1e-5f

// ---------------------------------------------------------------------------
// Static scratch (no allocation allowed in kernel_launch)
// ---------------------------------------------------------------------------
__device__ float g_xln [NTOK * HIDDEN];   // LN1 output
__device__ float g_q   [NTOK * HIDDEN];   // Q proj (layout [t, h*64+d])
__device__ float g_k   [NTOK * HIDDEN];
__device__ float g_v   [NTOK * HIDDEN];
__device__ float g_ctx [NTOK * HIDDEN];   // attention context
__device__ float g_h   [NTOK * HIDDEN];   // residual + attn_out
__device__ float g_yln [NTOK * HIDDEN];   // LN2 output
__device__ float g_gate[NTOK * DFF];      // gate proj -> reused for activation
__device__ float g_up  [NTOK * DFF];      // up proj

// ---------------------------------------------------------------------------
// LayerNorm: one block per token, 256 threads
// ---------------------------------------------------------------------------
__global__ __launch_bounds__(256) void ln_kernel(
    const float* __restrict__ x, const float* __restrict__ w,
    const float* __restrict__ b, float* __restrict__ out)
{
    int t = blockIdx.x;
    const float* xr = x + (size_t)t * HIDDEN;
    float* orow = out + (size_t)t * HIDDEN;

    float s = 0.f, ss = 0.f;
    for (int i = threadIdx.x; i < HIDDEN; i += 256) {
        float v = xr[i];
        s += v; ss += v * v;
    }
    __shared__ float red_s[8], red_ss[8];
    #pragma unroll
    for (int o = 16; o; o >>= 1) {
        s  += __shfl_xor_sync(0xffffffffu, s,  o);
        ss += __shfl_xor_sync(0xffffffffu, ss, o);
    }
    int wid = threadIdx.x >> 5, lid = threadIdx.x & 31;
    if (lid == 0) { red_s[wid] = s; red_ss[wid] = ss; }
    __syncthreads();
    if (wid == 0) {
        s  = (lid < 8) ? red_s[lid]  : 0.f;
        ss = (lid < 8) ? red_ss[lid] : 0.f;
        #pragma unroll
        for (int o = 4; o; o >>= 1) {
            s  += __shfl_xor_sync(0xffffffffu, s,  o);
            ss += __shfl_xor_sync(0xffffffffu, ss, o);
        }
        if (lid == 0) { red_s[0] = s * (1.f / HIDDEN); red_ss[0] = ss * (1.f / HIDDEN); }
    }
    __syncthreads();
    float mu  = red_s[0];
    float var = red_ss[0] - mu * mu;
    float inv = rsqrtf(var + EPS);
    for (int i = threadIdx.x; i < HIDDEN; i += 256)
        orow[i] = (xr[i] - mu) * inv * w[i] + b[i];
}

// ---------------------------------------------------------------------------
// tf32 helpers
// ---------------------------------------------------------------------------
__device__ __forceinline__ float tf32r(float x) {
    uint32_t u;
    asm("cvt.rn.tf32.f32 %0, %1;" : "=r"(u) : "f"(x));
    return __uint_as_float(u);
}

__device__ __forceinline__ void mma_tf32(
    float4& c, const uint32_t a[4], const uint32_t b[2])
{
    asm volatile(
        "mma.sync.aligned.m16n8k8.row.col.f32.tf32.tf32.f32 "
        "{%0,%1,%2,%3}, {%4,%5,%6,%7}, {%8,%9}, {%0,%1,%2,%3};\n"
        : "+f"(c.x), "+f"(c.y), "+f"(c.z), "+f"(c.w)
        : "r"(a[0]), "r"(a[1]), "r"(a[2]), "r"(a[3]),
          "r"(b[0]), "r"(b[1]));
}

// ---------------------------------------------------------------------------
// Tensor-core GEMM (NT): C[M,N] = A[M,K] * B[N,K]^T  (+ optional add)
// A row-major [M,K], B row-major [N,K] (== col-major k x n operand).
// 128x128 CTA tile, 256 threads, 8 warps as 2(m) x 4(n), warp tile 64x32,
// BK=16, m16n8k8 tf32 MMA, smem stride 20 (conflict-free fragment loads),
// register prefetch of next global tile.
// All dims are multiples of 128/16 here, no edge guards.
// ---------------------------------------------------------------------------
#define TBM 128
#define TBN 128
#define TBK 16
#define SKA 20   // padded k-stride in words: g*20 + tg hits 32 distinct banks

__global__ __launch_bounds__(256) void tgemm_nt(
    const float* __restrict__ A, const float* __restrict__ B,
    float* __restrict__ C, const float* __restrict__ add,
    int M, int N, int K)
{
    __shared__ __align__(16) float As[TBM * SKA];
    __shared__ __align__(16) float Bs[TBN * SKA];

    int tid  = threadIdx.x;
    int warp = tid >> 5, lane = tid & 31;
    int g  = lane >> 2;        // 0..7
    int tg = lane & 3;         // 0..3
    int wm = (warp & 1) * 64;  // warp m-offset
    int wn = (warp >> 1) * 32; // warp n-offset
    int m0 = blockIdx.y * TBM;
    int n0 = blockIdx.x * TBN;

    float4 acc[4][4];
    #pragma unroll
    for (int i = 0; i < 4; i++)
        #pragma unroll
        for (int j = 0; j < 4; j++)
            acc[i][j] = make_float4(0.f, 0.f, 0.f, 0.f);

    // global load mapping: rows tid/4 and tid/4+64, cols (tid%4)*4
    int lrow = tid >> 2;
    int lcol = (tid & 3) * 4;
    const float* Ap = A + (size_t)(m0 + lrow) * K + lcol;
    const float* Bp = B + (size_t)(n0 + lrow) * K + lcol;

    float4 pa0 = *(const float4*)(Ap);
    float4 pa1 = *(const float4*)(Ap + (size_t)64 * K);
    float4 pb0 = *(const float4*)(Bp);
    float4 pb1 = *(const float4*)(Bp + (size_t)64 * K);

    for (int k0 = 0; k0 < K; k0 += TBK) {
        // commit prefetched tile to smem (pre-rounded to tf32)
        float4 t;
        t = make_float4(tf32r(pa0.x), tf32r(pa0.y), tf32r(pa0.z), tf32r(pa0.w));
        *(float4*)&As[lrow * SKA + lcol] = t;
        t = make_float4(tf32r(pa1.x), tf32r(pa1.y), tf32r(pa1.z), tf32r(pa1.w));
        *(float4*)&As[(lrow + 64) * SKA + lcol] = t;
        t = make_float4(tf32r(pb0.x), tf32r(pb0.y), tf32r(pb0.z), tf32r(pb0.w));
        *(float4*)&Bs[lrow * SKA + lcol] = t;
        t = make_float4(tf32r(pb1.x), tf32r(pb1.y), tf32r(pb1.z), tf32r(pb1.w));
        *(float4*)&Bs[(lrow + 64) * SKA + lcol] = t;
        __syncthreads();

        int kn = k0 + TBK;
        if (kn < K) {
            pa0 = *(const float4*)(Ap + kn);
            pa1 = *(const float4*)(Ap + (size_t)64 * K + kn);
            pb0 = *(const float4*)(Bp + kn);
            pb1 = *(const float4*)(Bp + (size_t)64 * K + kn);
        }

        #pragma unroll
        for (int ks = 0; ks < 2; ks++) {
            int kb = ks * 8;
            uint32_t af[4][4], bf[4][2];
            #pragma unroll
            for (int mt = 0; mt < 4; mt++) {
                int r = wm + mt * 16 + g;
                af[mt][0] = __float_as_uint(As[r * SKA + kb + tg]);
                af[mt][1] = __float_as_uint(As[(r + 8) * SKA + kb + tg]);
                af[mt][2] = __float_as_uint(As[r * SKA + kb + tg + 4]);
                af[mt][3] = __float_as_uint(As[(r + 8) * SKA + kb + tg + 4]);
            }
            #pragma unroll
            for (int nt = 0; nt < 4; nt++) {
                int rn = wn + nt * 8 + g;
                bf[nt][0] = __float_as_uint(Bs[rn * SKA + kb + tg]);
                bf[nt][1] = __float_as_uint(Bs[rn * SKA + kb + tg + 4]);
            }
            #pragma unroll
            for (int mt = 0; mt < 4; mt++)
                #pragma unroll
                for (int nt = 0; nt < 4; nt++)
                    mma_tf32(acc[mt][nt], af[mt], bf[nt]);
        }
        __syncthreads();
    }

    // epilogue: c0/c1 -> row g, cols 2tg,2tg+1 ; c2/c3 -> row g+8
    #pragma unroll
    for (int mt = 0; mt < 4; mt++) {
        int m = m0 + wm + mt * 16 + g;
        #pragma unroll
        for (int nt = 0; nt < 4; nt++) {
            int n = n0 + wn + nt * 8 + 2 * tg;
            float2 r0 = make_float2(acc[mt][nt].x, acc[mt][nt].y);
            float2 r1 = make_float2(acc[mt][nt].z, acc[mt][nt].w);
            if (add) {
                float2 a0 = *(const float2*)(add + (size_t)m * N + n);
                float2 a1 = *(const float2*)(add + (size_t)(m + 8) * N + n);
                r0.x += a0.x; r0.y += a0.y;
                r1.x += a1.x; r1.y += a1.y;
            }
            *(float2*)(C + (size_t)m * N + n)       = r0;
            *(float2*)(C + (size_t)(m + 8) * N + n) = r1;
        }
    }
}

// ---------------------------------------------------------------------------
// RoPE in-place on first ROT dims of every head. One thread per (token, head).
// ---------------------------------------------------------------------------
__global__ void rope_kernel(float* __restrict__ qk, const int* __restrict__ pos_ids)
{
    int idx = blockIdx.x * blockDim.x + threadIdx.x;
    if (idx >= NTOK * NHEADS) return;
    int t = idx / NHEADS, h = idx % NHEADS;
    float pos = (float)pos_ids[t];
    float* p = qk + (size_t)t * HIDDEN + h * HDIM;

    float x[ROT];
    #pragma unroll
    for (int j = 0; j < ROT; j++) x[j] = p[j];

    #pragma unroll
    for (int i = 0; i < ROT / 2; i++) {
        float invf = powf(10000.f, -(float)i / (ROT / 2));
        float f = pos * invf;
        float c = cosf(f), s = sinf(f);
        float lo = x[i], hi = x[i + ROT / 2];
        p[i]           = lo * c - hi * s;
        p[i + ROT / 2] = hi * c + lo * s;
    }
}

// ---------------------------------------------------------------------------
// Flash attention fp32. One block = (128 q-rows, one head, one batch).
// One thread owns one q-row: q[64] and o[64] in registers, online softmax.
// ---------------------------------------------------------------------------
#define BQ  128
#define BKT 32

__global__ __launch_bounds__(128) void attn_kernel(const float* __restrict__ mask)
{
    __shared__ __align__(16) float Ks[BKT][HDIM];
    __shared__ __align__(16) float Vs[BKT][HDIM];
    __shared__ float Ms[BQ][BKT + 1];

    int b  = blockIdx.z;
    int h  = blockIdx.y;
    int q0 = blockIdx.x * BQ;
    int tid = threadIdx.x;
    int qi = q0 + tid;
    int t  = b * SQ + qi;

    const float* qrow  = g_q + (size_t)t * HIDDEN + h * HDIM;
    const float* kbase = g_k + (size_t)(b * SQ) * HIDDEN + h * HDIM;
    const float* vbase = g_v + (size_t)(b * SQ) * HIDDEN + h * HDIM;

    float4 qv[16], ov[16];
    #pragma unroll
    for (int i = 0; i < 16; i++) {
        qv[i] = *(const float4*)(qrow + i * 4);
        ov[i] = make_float4(0.f, 0.f, 0.f, 0.f);
    }
    float m = -1e30f, l = 0.f;
    const float scale = 0.125f;

    for (int k0 = 0; k0 < SQ; k0 += BKT) {
        for (int i = tid * 4; i < BKT * HDIM; i += 128 * 4) {
            int r = i >> 6, c = i & 63;
            *(float4*)&Ks[r][c] = *(const float4*)(kbase + (size_t)(k0 + r) * HIDDEN + c);
            *(float4*)&Vs[r][c] = *(const float4*)(vbase + (size_t)(k0 + r) * HIDDEN + c);
        }
        for (int i = tid * 4; i < BQ * BKT; i += 128 * 4) {
            int r = i >> 5, c = i & 31;
            float4 mv = *(const float4*)(mask + ((size_t)(b * SQ + q0 + r)) * SQ + k0 + c);
            Ms[r][c + 0] = mv.x; Ms[r][c + 1] = mv.y;
            Ms[r][c + 2] = mv.z; Ms[r][c + 3] = mv.w;
        }
        __syncthreads();

        float sc[BKT];
        float tmax = m;
        #pragma unroll
        for (int kj = 0; kj < BKT; kj++) {
            float s = 0.f;
            #pragma unroll
            for (int d4 = 0; d4 < 16; d4++) {
                float4 kv = *(const float4*)&Ks[kj][d4 * 4];
                s = fmaf(qv[d4].x, kv.x, s);
                s = fmaf(qv[d4].y, kv.y, s);
                s = fmaf(qv[d4].z, kv.z, s);
                s = fmaf(qv[d4].w, kv.w, s);
            }
            s = s * scale + Ms[tid][kj];
            sc[kj] = s;
            tmax = fmaxf(tmax, s);
        }
        float corr = expf(m - tmax);
        m = tmax;
        l *= corr;
        #pragma unroll
        for (int i = 0; i < 16; i++) {
            ov[i].x *= corr; ov[i].y *= corr; ov[i].z *= corr; ov[i].w *= corr;
        }
        #pragma unroll
        for (int kj = 0; kj < BKT; kj++) {
            float e = expf(sc[kj] - m);
            l += e;
            #pragma unroll
            for (int d4 = 0; d4 < 16; d4++) {
                float4 vv = *(const float4*)&Vs[kj][d4 * 4];
                ov[d4].x = fmaf(e, vv.x, ov[d4].x);
                ov[d4].y = fmaf(e, vv.y, ov[d4].y);
                ov[d4].z = fmaf(e, vv.z, ov[d4].z);
                ov[d4].w = fmaf(e, vv.w, ov[d4].w);
            }
        }
        __syncthreads();
    }

    float inv = 1.f / l;
    float* orow = g_ctx + (size_t)t * HIDDEN + h * HDIM;
    #pragma unroll
    for (int i = 0; i < 16; i++) {
        float4 r = make_float4(ov[i].x * inv, ov[i].y * inv, ov[i].z * inv, ov[i].w * inv);
        *(float4*)(orow + i * 4) = r;
    }
}

// ---------------------------------------------------------------------------
// SwiGLU activation: g = silu(g) * u, elementwise, vectorized
// ---------------------------------------------------------------------------
__global__ void silu_mul_kernel(float* __restrict__ g, const float* __restrict__ u, int n4)
{
    int i = blockIdx.x * blockDim.x + threadIdx.x;
    if (i >= n4) return;
    float4 gv = ((const float4*)g)[i];
    float4 uv = ((const float4*)u)[i];
    gv.x = gv.x / (1.f + expf(-gv.x)) * uv.x;
    gv.y = gv.y / (1.f + expf(-gv.y)) * uv.y;
    gv.z = gv.z / (1.f + expf(-gv.z)) * uv.z;
    gv.w = gv.w / (1.f + expf(-gv.w)) * uv.w;
    ((float4*)g)[i] = gv;
}

// ---------------------------------------------------------------------------
// Launch
// Inputs (metadata order): hidden_states, memory, attention_mask, position_ids,
// Wq, Wk, Wv, Wo, ln1_w, ln1_b, ln2_w, ln2_b, gate_w, up_w, down_w
// ---------------------------------------------------------------------------
extern "C" void kernel_launch(void* const* d_in, const int* in_sizes, int n_in,
                              void* d_out, int out_size)
{
    const float* hs    = (const float*)d_in[0];
    const float* mem   = (const float*)d_in[1];
    const float* mask  = (const float*)d_in[2];
    const int*   pos   = (const int*)  d_in[3];
    const float* Wq    = (const float*)d_in[4];
    const float* Wk    = (const float*)d_in[5];
    const float* Wv    = (const float*)d_in[6];
    const float* Wo    = (const float*)d_in[7];
    const float* ln1w  = (const float*)d_in[8];
    const float* ln1b  = (const float*)d_in[9];
    const float* ln2w  = (const float*)d_in[10];
    const float* ln2b  = (const float*)d_in[11];
    const float* gatew = (const float*)d_in[12];
    const float* upw   = (const float*)d_in[13];
    const float* downw = (const float*)d_in[14];
    float* out = (float*)d_out;

    float *xln, *q, *k, *v, *ctx, *h, *yln, *gate, *up;
    cudaGetSymbolAddress((void**)&xln,  g_xln);
    cudaGetSymbolAddress((void**)&q,    g_q);
    cudaGetSymbolAddress((void**)&k,    g_k);
    cudaGetSymbolAddress((void**)&v,    g_v);
    cudaGetSymbolAddress((void**)&ctx,  g_ctx);
    cudaGetSymbolAddress((void**)&h,    g_h);
    cudaGetSymbolAddress((void**)&yln,  g_yln);
    cudaGetSymbolAddress((void**)&gate, g_gate);
    cudaGetSymbolAddress((void**)&up,   g_up);

    // 1. LN1
    ln_kernel<<<NTOK, 256>>>(hs, ln1w, ln1b, xln);

    // 2. Q/K/V projections (NT gemm: x @ W^T) — tf32 tensor cores
    dim3 g2048(HIDDEN / TBN, NTOK / TBM);
    tgemm_nt<<<g2048, 256>>>(xln, Wq, q, nullptr, NTOK, HIDDEN, HIDDEN);
    tgemm_nt<<<g2048, 256>>>(mem, Wk, k, nullptr, NTOK, HIDDEN, HIDDEN);
    tgemm_nt<<<g2048, 256>>>(mem, Wv, v, nullptr, NTOK, HIDDEN, HIDDEN);

    // 3. RoPE on q and k
    int nrope = NTOK * NHEADS;
    rope_kernel<<<(nrope + 255) / 256, 256>>>(q, pos);
    rope_kernel<<<(nrope + 255) / 256, 256>>>(k, pos);

    // 4. Attention
    attn_kernel<<<dim3(SQ / BQ, NHEADS, BATCH), 128>>>(mask);

    // 5. O projection + residual  (h = hs + ctx @ Wo^T)
    tgemm_nt<<<g2048, 256>>>(ctx, Wo, h, hs, NTOK, HIDDEN, HIDDEN);

    // 6. LN2
    ln_kernel<<<NTOK, 256>>>(h, ln2w, ln2b, yln);

    // 7. MLP gate/up
    dim3 g8192(DFF / TBN, NTOK / TBM);
    tgemm_nt<<<g8192, 256>>>(yln, gatew, gate, nullptr, NTOK, DFF, HIDDEN);
    tgemm_nt<<<g8192, 256>>>(yln, upw,   up,   nullptr, NTOK, DFF, HIDDEN);

    // 8. silu(gate) * up  -> gate (in place)
    int n4 = NTOK * DFF / 4;
    silu_mul_kernel<<<(n4 + 255) / 256, 256>>>(gate, up, n4);

    // 9. down projection + residual -> out
    tgemm_nt<<<g2048, 256>>>(gate, downw, out, h, NTOK, HIDDEN, DFF);

    (void)in_sizes; (void)n_in; (void)out_size;
}